// round 5
// baseline (speedup 1.0000x reference)
#include <cuda_runtime.h>
#include <stdint.h>
#include <math.h>

#define NB 64
#define NH 1024
#define NV 32000
#define NT 31
#define G4H 4096

__device__ float g_W2[NH * G4H];
__device__ float g_z[2 * NB * G4H];
__device__ float g_h[NB * NH];
__device__ float g_c[NB * NH];
__device__ float g_logits[NB * NV];
__device__ float4 g_red[NB * 8];
__device__ float g_m[NB];
__device__ float g_logS[NB];
__device__ float g_aval[NB * 8];
__device__ int   g_aidx[NB * 8];
__device__ float g_alp[NB * 8];

__device__ __forceinline__ float negInf() { return __int_as_float(0xff800000); }

// exact JAX threefry2x32 (20 rounds)
__device__ __forceinline__ void tf2x32(uint32_t k0, uint32_t k1,
                                       uint32_t x0, uint32_t x1,
                                       uint32_t& o0, uint32_t& o1) {
    uint32_t k2 = k0 ^ k1 ^ 0x1BD11BDAu;
    x0 += k0; x1 += k1;
#define TFR(r) { x0 += x1; x1 = (x1 << (r)) | (x1 >> (32 - (r))); x1 ^= x0; }
    TFR(13) TFR(15) TFR(26) TFR(6)
    x0 += k1; x1 += k2 + 1u;
    TFR(17) TFR(29) TFR(16) TFR(24)
    x0 += k2; x1 += k0 + 2u;
    TFR(13) TFR(15) TFR(26) TFR(6)
    x0 += k0; x1 += k1 + 3u;
    TFR(17) TFR(29) TFR(16) TFR(24)
    x0 += k1; x1 += k2 + 4u;
    TFR(13) TFR(15) TFR(26) TFR(6)
    x0 += k2; x1 += k0 + 5u;
#undef TFR
    o0 = x0; o1 = x1;
}

// JAX uniform(tiny,1): bits -> [tiny, 1)
__device__ __forceinline__ float u01(uint32_t b) {
    float f = __uint_as_float((b >> 9) | 0x3f800000u) - 1.0f;
    return fmaxf(f, 1.17549435e-38f);
}

__global__ void k_init(float* __restrict__ out) {
    int i = blockIdx.x * blockDim.x + threadIdx.x;
    if (i < NB * NH) g_c[i] = 0.f;
    if (i < 3 * NB * 2 * NT) out[i] = 0.f;
}

__global__ void k_addw(const float* __restrict__ a, const float* __restrict__ b) {
    int i = blockIdx.x * blockDim.x + threadIdx.x;
    if (i < NH * G4H) g_W2[i] = a[i] + b[i];
}

// C(64xN) = A(64xK) @ B(KxN); gridDim.y = K-split count (partials at C + ks*64*N);
// bias added only when un-split.
__global__ __launch_bounds__(256) void gemm64(const float* __restrict__ A,
                                              const float* __restrict__ B,
                                              const float* __restrict__ bias,
                                              float* __restrict__ C,
                                              int K, int N) {
    __shared__ float As[16][68];
    __shared__ float Bs[16][68];
    const int tid = threadIdx.x;
    const int n0 = blockIdx.x * 64;
    const int tc = (tid & 15) * 4;
    const int tr = (tid >> 4) * 4;
    const int ar = tid >> 2;
    const int ak = (tid & 3) * 4;
    const int br = tid >> 4;
    const int bc = (tid & 15) * 4;
    const int KS = gridDim.y;
    const int kPer = K / KS;
    const int kBeg = blockIdx.y * kPer;
    const int kEnd = kBeg + kPer;
    float* Cb = C + (size_t)blockIdx.y * 64 * (size_t)N;

    float acc[4][4] = {};
    for (int k0 = kBeg; k0 < kEnd; k0 += 16) {
        float4 av = *(const float4*)(A + ar * K + k0 + ak);
        As[ak + 0][ar] = av.x; As[ak + 1][ar] = av.y;
        As[ak + 2][ar] = av.z; As[ak + 3][ar] = av.w;
        *(float4*)&Bs[br][bc] = *(const float4*)(B + (size_t)(k0 + br) * N + n0 + bc);
        __syncthreads();
#pragma unroll
        for (int k = 0; k < 16; k++) {
            float4 a = *(const float4*)&As[k][tr];
            float4 b = *(const float4*)&Bs[k][tc];
            acc[0][0] = fmaf(a.x, b.x, acc[0][0]);
            acc[0][1] = fmaf(a.x, b.y, acc[0][1]);
            acc[0][2] = fmaf(a.x, b.z, acc[0][2]);
            acc[0][3] = fmaf(a.x, b.w, acc[0][3]);
            acc[1][0] = fmaf(a.y, b.x, acc[1][0]);
            acc[1][1] = fmaf(a.y, b.y, acc[1][1]);
            acc[1][2] = fmaf(a.y, b.z, acc[1][2]);
            acc[1][3] = fmaf(a.y, b.w, acc[1][3]);
            acc[2][0] = fmaf(a.z, b.x, acc[2][0]);
            acc[2][1] = fmaf(a.z, b.y, acc[2][1]);
            acc[2][2] = fmaf(a.z, b.z, acc[2][2]);
            acc[2][3] = fmaf(a.z, b.w, acc[2][3]);
            acc[3][0] = fmaf(a.w, b.x, acc[3][0]);
            acc[3][1] = fmaf(a.w, b.y, acc[3][1]);
            acc[3][2] = fmaf(a.w, b.z, acc[3][2]);
            acc[3][3] = fmaf(a.w, b.w, acc[3][3]);
        }
        __syncthreads();
    }
    float4 bv = make_float4(0.f, 0.f, 0.f, 0.f);
    if (KS == 1) bv = *(const float4*)(bias + n0 + tc);
#pragma unroll
    for (int i = 0; i < 4; i++) {
        float4 o;
        o.x = acc[i][0] + bv.x; o.y = acc[i][1] + bv.y;
        o.z = acc[i][2] + bv.z; o.w = acc[i][3] + bv.w;
        *(float4*)(Cb + (size_t)(tr + i) * N + n0 + tc) = o;
    }
}

// LSTM gates (i,f,g,o), activation=None: c'=sig(f)*c+sig(i)*g ; h'=sig(o)*c'
// sigmoids in double for ulp-accuracy (immune to fast-math), products in rn fp32.
__global__ void k_gates(const float* __restrict__ bias, int KS) {
    int idx = blockIdx.x * blockDim.x + threadIdx.x;  // 65536
    int b = idx >> 10, j = idx & 1023;
    float zi = bias[j], zf = bias[j + 1024], zg = bias[j + 2048], zo = bias[j + 3072];
    for (int s = 0; s < KS; s++) {
        const float* z = g_z + s * NB * G4H + (b << 12);
        zi = __fadd_rn(zi, z[j]);
        zf = __fadd_rn(zf, z[j + 1024]);
        zg = __fadd_rn(zg, z[j + 2048]);
        zo = __fadd_rn(zo, z[j + 3072]);
    }
    float si = (float)(1.0 / (1.0 + exp(-(double)zi)));
    float sf = (float)(1.0 / (1.0 + exp(-(double)zf)));
    float so = (float)(1.0 / (1.0 + exp(-(double)zo)));
    float cn = __fadd_rn(__fmul_rn(sf, g_c[idx]), __fmul_rn(si, zg));
    g_c[idx] = cn;
    g_h[idx] = __fmul_rn(so, cn);
}

__device__ __forceinline__ void softmerge(float& m, float& S, float& T,
                                          float m2, float S2, float T2) {
    if (S2 == 0.f) return;
    if (S == 0.f) { m = m2; S = S2; T = T2; return; }
    if (m2 > m) {
        float t;
        t = m; m = m2; m2 = t;
        t = S; S = S2; S2 = t;
        t = T; T = T2; T2 = t;
    }
    float e = expf(m2 - m);
    S += S2 * e;
    T += (T2 + (m2 - m) * S2) * e;
}

// pass 1: per-(row, V-slice) online (max, sum e^(l-m), sum (l-m)e^(l-m))
__global__ __launch_bounds__(256) void k_redpart() {
    int slice = blockIdx.x;   // 0..7
    int row   = blockIdx.y;   // 0..63
    int tid   = threadIdx.x;
    const float* lrow = g_logits + row * NV;
    int v0 = slice * 4000, v1 = v0 + 4000;
    float m = negInf(), S = 0.f, T = 0.f;
    for (int v = v0 + tid; v < v1; v += 256) {
        float l = lrow[v];
        if (S == 0.f) { m = l; S = 1.f; T = 0.f; }
        else if (l > m) {
            float e = expf(m - l);
            T = (T + (m - l) * S) * e;
            S = S * e + 1.f;
            m = l;
        } else {
            float d = l - m, e = expf(d);
            S += e; T += d * e;
        }
    }
    for (int o = 16; o; o >>= 1) {
        float m2 = __shfl_down_sync(0xffffffffu, m, o);
        float S2 = __shfl_down_sync(0xffffffffu, S, o);
        float T2 = __shfl_down_sync(0xffffffffu, T, o);
        softmerge(m, S, T, m2, S2, T2);
    }
    __shared__ float sm[8], sS[8], sT[8];
    if ((tid & 31) == 0) { sm[tid >> 5] = m; sS[tid >> 5] = S; sT[tid >> 5] = T; }
    __syncthreads();
    if (tid == 0) {
        float fm = sm[0], fS = sS[0], fT = sT[0];
        for (int w = 1; w < 8; w++) softmerge(fm, fS, fT, sm[w], sS[w], sT[w]);
        g_red[row * 8 + slice] = make_float4(fm, fS, fT, 0.f);
    }
}

// finalize: m, logS per row; entropy = logS - T/S
__global__ void k_redfin(float* __restrict__ out, int t) {
    int row = threadIdx.x;
    if (row >= NB) return;
    float m = negInf(), S = 0.f, T = 0.f;
    for (int s = 0; s < 8; s++) {
        float4 p = g_red[row * 8 + s];
        softmerge(m, S, T, p.x, p.y, p.z);
    }
    float logS = (float)log((double)S);
    g_m[row] = m;
    g_logS[row] = logS;
    out[2 * NB * 2 * NT + row * (2 * NT) + t] = logS - T / S;
}

// pass 2: gumbel argmax of logp+g.
// PARTITIONABLE threefry (JAX >= 0.4.30 default): element (b,v) with flat
// index i = b*NV+v gets bits = o0 ^ o1 of threefry2x32(kk, hi32(i)=0, lo32(i)=i).
__global__ __launch_bounds__(256) void k_samp(int t) {
    int slice = blockIdx.x;    // 0..7
    int row   = blockIdx.y;    // 0..63
    int tid   = threadIdx.x;
    uint32_t kk0, kk1;
    tf2x32(0u, 1234u, 0u, (uint32_t)t, kk0, kk1);   // fold_in(key(1234), t)
    float m = g_m[row], lS = g_logS[row];
    const float* lrow = g_logits + row * NV;
    float best = negInf(), blp = 0.f; int bidx = 0x7fffffff;
    int v0 = slice * 4000, v1 = v0 + 4000;
    for (int v = v0 + tid; v < v1; v += 256) {
        uint32_t i = (uint32_t)(row * NV + v);
        uint32_t o0, o1;
        tf2x32(kk0, kk1, 0u, i, o0, o1);
        float u = u01(o0 ^ o1);
        // -log(-log(u)) in double: safe for u -> 1 tail even under fast-math
        float g = (float)(-log(-log((double)u)));
        float lp = __fadd_rn(__fadd_rn(lrow[v], -m), -lS);
        float s = __fadd_rn(g, lp);
        if (s > best || (s == best && v < bidx)) { best = s; bidx = v; blp = lp; }
    }
    for (int o = 16; o; o >>= 1) {
        float v2 = __shfl_down_sync(0xffffffffu, best, o);
        int   i2 = __shfl_down_sync(0xffffffffu, bidx, o);
        float l2 = __shfl_down_sync(0xffffffffu, blp, o);
        if (v2 > best || (v2 == best && i2 < bidx)) { best = v2; bidx = i2; blp = l2; }
    }
    __shared__ float sv[8]; __shared__ int si[8]; __shared__ float sl[8];
    if ((tid & 31) == 0) { int w = tid >> 5; sv[w] = best; si[w] = bidx; sl[w] = blp; }
    __syncthreads();
    if (tid == 0) {
        float bv = sv[0]; int bi = si[0]; float bl = sl[0];
        for (int w = 1; w < 8; w++)
            if (sv[w] > bv || (sv[w] == bv && si[w] < bi)) {
                bv = sv[w]; bi = si[w]; bl = sl[w];
            }
        g_aval[row * 8 + slice] = bv;
        g_aidx[row * 8 + slice] = bi;
        g_alp[row * 8 + slice]  = bl;
    }
}

__global__ void k_argfin(float* __restrict__ out, int t) {
    int row = threadIdx.x;
    if (row >= NB) return;
    float bv = negInf(); int bi = 0x7fffffff; float bl = 0.f;
    for (int s = 0; s < 8; s++) {
        float v = g_aval[row * 8 + s];
        int   i = g_aidx[row * 8 + s];
        if (v > bv || (v == bv && i < bi)) { bv = v; bi = i; bl = g_alp[row * 8 + s]; }
    }
    out[row * (2 * NT) + t] = (float)bi;                    // msg
    out[NB * 2 * NT + row * (2 * NT) + t] = bl;             // log_prob
}

__global__ void k_copyh(float* __restrict__ out) {
    int i = blockIdx.x * blockDim.x + threadIdx.x;
    if (i < NB * NH) out[3 * NB * 2 * NT + i] = g_h[i];
}

extern "C" void kernel_launch(void* const* d_in, const int* in_sizes, int n_in,
                              void* d_out, int out_size) {
    // Size-based dispatch (robust to metadata ordering):
    //  32768 -> inp ; 2097152 -> Wx1 ; 4194304 x3 -> {Wh1 (first, unused), Wx2, Wh2}
    //  32768000 -> Wd ; 32000 -> bd ; 4096 x2 -> b1 then b2 (both zero anyway)
    const float *inp = 0, *Wx1 = 0, *Wd = 0, *bd = 0, *b1 = 0, *b2 = 0;
    const float* w4[3] = {0, 0, 0};
    int n4 = 0;
    for (int i = 0; i < n_in; i++) {
        const float* p = (const float*)d_in[i];
        switch (in_sizes[i]) {
            case 32768:    inp = p; break;
            case 2097152:  Wx1 = p; break;
            case 4194304:  if (n4 < 3) w4[n4++] = p; break;
            case 32768000: Wd = p; break;
            case 32000:    bd = p; break;
            case 4096:     if (!b1) b1 = p; else b2 = p; break;
            default: break;
        }
    }
    // w4[0] = Wh1 (unused: encoder h0 = 0); W2 = w4[1] + w4[2] (commutative)
    float* out = (float*)d_out;

    void *pz, *plog, *ph, *pw2;
    cudaGetSymbolAddress(&pz, g_z);
    cudaGetSymbolAddress(&plog, g_logits);
    cudaGetSymbolAddress(&ph, g_h);
    cudaGetSymbolAddress(&pw2, g_W2);
    float* z  = (float*)pz;
    float* lg = (float*)plog;
    float* h  = (float*)ph;
    float* W2 = (float*)pw2;

    k_init<<<256, 256>>>(out);
    k_addw<<<(NH * G4H) / 256, 256>>>(w4[1], w4[2]);

    // encoder: one step, zero state -> z = inp @ Wx1 + b1
    gemm64<<<dim3(64, 2), 256>>>(inp, Wx1, b1, z, 512, G4H);
    k_gates<<<256, 256>>>(b1, 2);

    for (int t = 0; t < NT; t++) {
        gemm64<<<dim3(64, 2), 256>>>(h, W2, b2, z, NH, G4H);
        k_gates<<<256, 256>>>(b2, 2);
        gemm64<<<dim3(500, 1), 256>>>(h, Wd, bd, lg, NH, NV);
        k_redpart<<<dim3(8, 64), 256>>>();
        k_redfin<<<1, 64>>>(out, t);
        k_samp<<<dim3(8, 64), 256>>>(t);
        k_argfin<<<1, 64>>>(out, t);
    }
    k_copyh<<<256, 256>>>(out);
}

// round 6
// speedup vs baseline: 1.0644x; 1.0644x over previous
#include <cuda_runtime.h>
#include <stdint.h>
#include <math.h>

#define NB 64
#define NH 1024
#define NV 32000
#define NT 31
#define G4H 4096

__device__ float g_W2[NH * G4H];
__device__ float g_z[2 * NB * G4H];
__device__ float g_h[NB * NH];
__device__ float g_c[NB * NH];
__device__ float g_logits[NB * NV];
__device__ float4 g_red[NB * 8];
__device__ float g_aval[NT * NB * 8];
__device__ int   g_aidx[NT * NB * 8];
__device__ float g_alp[NT * NB * 8];

__device__ __forceinline__ float negInf() { return __int_as_float(0xff800000); }

// ---- packed f32x2 FMA (sm_103a): two independent rn-FMAs per instruction ----
__device__ __forceinline__ unsigned long long pk2(float x) {
    unsigned long long r;
    asm("mov.b64 %0, {%1, %1};" : "=l"(r) : "f"(x));
    return r;
}
__device__ __forceinline__ void fma2(unsigned long long& c, unsigned long long a,
                                     unsigned long long b) {
    asm("fma.rn.f32x2 %0, %1, %2, %0;" : "+l"(c) : "l"(a), "l"(b));
}
__device__ __forceinline__ float lo32(unsigned long long v) {
    return __uint_as_float((unsigned)v);
}
__device__ __forceinline__ float hi32(unsigned long long v) {
    return __uint_as_float((unsigned)(v >> 32));
}

// exact JAX threefry2x32 (20 rounds)
__device__ __forceinline__ void tf2x32(uint32_t k0, uint32_t k1,
                                       uint32_t x0, uint32_t x1,
                                       uint32_t& o0, uint32_t& o1) {
    uint32_t k2 = k0 ^ k1 ^ 0x1BD11BDAu;
    x0 += k0; x1 += k1;
#define TFR(r) { x0 += x1; x1 = (x1 << (r)) | (x1 >> (32 - (r))); x1 ^= x0; }
    TFR(13) TFR(15) TFR(26) TFR(6)
    x0 += k1; x1 += k2 + 1u;
    TFR(17) TFR(29) TFR(16) TFR(24)
    x0 += k2; x1 += k0 + 2u;
    TFR(13) TFR(15) TFR(26) TFR(6)
    x0 += k0; x1 += k1 + 3u;
    TFR(17) TFR(29) TFR(16) TFR(24)
    x0 += k1; x1 += k2 + 4u;
    TFR(13) TFR(15) TFR(26) TFR(6)
    x0 += k2; x1 += k0 + 5u;
#undef TFR
    o0 = x0; o1 = x1;
}

__device__ __forceinline__ float u01(uint32_t b) {
    float f = __uint_as_float((b >> 9) | 0x3f800000u) - 1.0f;
    return fmaxf(f, 1.17549435e-38f);
}

__global__ void k_init(float* __restrict__ out) {
    int i = blockIdx.x * blockDim.x + threadIdx.x;
    if (i < NB * NH) g_c[i] = 0.f;
    if (i < 3 * NB * 2 * NT) out[i] = 0.f;
}

__global__ void k_addw(const float* __restrict__ a, const float* __restrict__ b) {
    int i = blockIdx.x * blockDim.x + threadIdx.x;
    if (i < NH * G4H) g_W2[i] = a[i] + b[i];
}

// C(64xN) = A(64xK) @ B(KxN); gridDim.y = K-split (partials at C + ks*64*N).
__global__ __launch_bounds__(256) void gemm64(const float* __restrict__ A,
                                              const float* __restrict__ B,
                                              const float* __restrict__ bias,
                                              float* __restrict__ C,
                                              int K, int N) {
    __shared__ float As[16][68];
    __shared__ float Bs[16][68];
    const int tid = threadIdx.x;
    const int n0 = blockIdx.x * 64;
    const int tc = (tid & 15) * 4;
    const int tr = (tid >> 4) * 4;
    const int ar = tid >> 2;
    const int ak = (tid & 3) * 4;
    const int br = tid >> 4;
    const int bc = (tid & 15) * 4;
    const int KS = gridDim.y;
    const int kPer = K / KS;
    const int kBeg = blockIdx.y * kPer;
    const int kEnd = kBeg + kPer;
    float* Cb = C + (size_t)blockIdx.y * 64 * (size_t)N;

    float acc[4][4] = {};
    for (int k0 = kBeg; k0 < kEnd; k0 += 16) {
        float4 av = *(const float4*)(A + ar * K + k0 + ak);
        As[ak + 0][ar] = av.x; As[ak + 1][ar] = av.y;
        As[ak + 2][ar] = av.z; As[ak + 3][ar] = av.w;
        *(float4*)&Bs[br][bc] = *(const float4*)(B + (size_t)(k0 + br) * N + n0 + bc);
        __syncthreads();
#pragma unroll
        for (int k = 0; k < 16; k++) {
            float4 a = *(const float4*)&As[k][tr];
            float4 b = *(const float4*)&Bs[k][tc];
            acc[0][0] = fmaf(a.x, b.x, acc[0][0]);
            acc[0][1] = fmaf(a.x, b.y, acc[0][1]);
            acc[0][2] = fmaf(a.x, b.z, acc[0][2]);
            acc[0][3] = fmaf(a.x, b.w, acc[0][3]);
            acc[1][0] = fmaf(a.y, b.x, acc[1][0]);
            acc[1][1] = fmaf(a.y, b.y, acc[1][1]);
            acc[1][2] = fmaf(a.y, b.z, acc[1][2]);
            acc[1][3] = fmaf(a.y, b.w, acc[1][3]);
            acc[2][0] = fmaf(a.z, b.x, acc[2][0]);
            acc[2][1] = fmaf(a.z, b.y, acc[2][1]);
            acc[2][2] = fmaf(a.z, b.z, acc[2][2]);
            acc[2][3] = fmaf(a.z, b.w, acc[2][3]);
            acc[3][0] = fmaf(a.w, b.x, acc[3][0]);
            acc[3][1] = fmaf(a.w, b.y, acc[3][1]);
            acc[3][2] = fmaf(a.w, b.z, acc[3][2]);
            acc[3][3] = fmaf(a.w, b.w, acc[3][3]);
        }
        __syncthreads();
    }
    float4 bv = make_float4(0.f, 0.f, 0.f, 0.f);
    if (KS == 1) bv = *(const float4*)(bias + n0 + tc);
#pragma unroll
    for (int i = 0; i < 4; i++) {
        float4 o;
        o.x = acc[i][0] + bv.x; o.y = acc[i][1] + bv.y;
        o.z = acc[i][2] + bv.z; o.w = acc[i][3] + bv.w;
        *(float4*)(Cb + (size_t)(tr + i) * N + n0 + tc) = o;
    }
}

// Logits GEMM: C(64x32000) = A(64x1024) @ B(1024x32000) + bias.
// 64x128 tile, 128 threads, 8x8 per thread, fma.rn.f32x2 inner product,
// register-prefetch software pipeline. Numerically identical to scalar rn-FMA.
__global__ __launch_bounds__(128) void gemmL(const float* __restrict__ A,
                                             const float* __restrict__ B,
                                             const float* __restrict__ bias,
                                             float* __restrict__ C) {
    __shared__ float As[16][68];
    __shared__ float Bs[16][132];
    const int tid = threadIdx.x;
    const int n0 = blockIdx.x * 128;
    const int tx = tid & 15;       // col group: cols tx*8 .. +8
    const int ty = tid >> 4;       // row group: rows ty*8 .. +8
    const int ar = tid >> 1;       // A staging row 0..63
    const int ak = (tid & 1) * 8;  // A staging k offset
    const int brow = tid >> 3;     // B staging k row 0..15
    const int bc0 = (tid & 7) * 4; // B staging col base

    unsigned long long acc[8][4];
#pragma unroll
    for (int i = 0; i < 8; i++)
#pragma unroll
        for (int j = 0; j < 4; j++) acc[i][j] = 0ull;

    // prologue: prefetch tile 0 into registers
    float4 pa0 = *(const float4*)(A + ar * NH + ak);
    float4 pa1 = *(const float4*)(A + ar * NH + ak + 4);
    float4 pb[4];
#pragma unroll
    for (int j = 0; j < 4; j++)
        pb[j] = *(const float4*)(B + (size_t)brow * NV + n0 + bc0 + j * 32);

    for (int k0 = 0; k0 < NH; k0 += 16) {
        As[ak + 0][ar] = pa0.x; As[ak + 1][ar] = pa0.y;
        As[ak + 2][ar] = pa0.z; As[ak + 3][ar] = pa0.w;
        As[ak + 4][ar] = pa1.x; As[ak + 5][ar] = pa1.y;
        As[ak + 6][ar] = pa1.z; As[ak + 7][ar] = pa1.w;
#pragma unroll
        for (int j = 0; j < 4; j++)
            *(float4*)&Bs[brow][bc0 + j * 32] = pb[j];
        __syncthreads();

        if (k0 + 16 < NH) {   // prefetch next tile (LDG latency hidden by compute)
            pa0 = *(const float4*)(A + ar * NH + k0 + 16 + ak);
            pa1 = *(const float4*)(A + ar * NH + k0 + 16 + ak + 4);
#pragma unroll
            for (int j = 0; j < 4; j++)
                pb[j] = *(const float4*)(B + (size_t)(k0 + 16 + brow) * NV + n0 + bc0 + j * 32);
        }

#pragma unroll
        for (int k = 0; k < 16; k++) {
            float4 a0 = *(const float4*)&As[k][ty * 8];
            float4 a1 = *(const float4*)&As[k][ty * 8 + 4];
            ulonglong2 b01 = *(const ulonglong2*)&Bs[k][tx * 8];
            ulonglong2 b23 = *(const ulonglong2*)&Bs[k][tx * 8 + 4];
            unsigned long long pa[8];
            pa[0] = pk2(a0.x); pa[1] = pk2(a0.y); pa[2] = pk2(a0.z); pa[3] = pk2(a0.w);
            pa[4] = pk2(a1.x); pa[5] = pk2(a1.y); pa[6] = pk2(a1.z); pa[7] = pk2(a1.w);
#pragma unroll
            for (int i = 0; i < 8; i++) {
                fma2(acc[i][0], pa[i], b01.x);
                fma2(acc[i][1], pa[i], b01.y);
                fma2(acc[i][2], pa[i], b23.x);
                fma2(acc[i][3], pa[i], b23.y);
            }
        }
        __syncthreads();
    }

    const float* bp = bias + n0 + tx * 8;
    float b0 = bp[0], b1 = bp[1], b2 = bp[2], b3 = bp[3];
    float b4 = bp[4], b5 = bp[5], b6 = bp[6], b7 = bp[7];
#pragma unroll
    for (int i = 0; i < 8; i++) {
        int row = ty * 8 + i;
        float* crow = C + (size_t)row * NV + n0 + tx * 8;
        float4 o0, o1;
        o0.x = lo32(acc[i][0]) + b0; o0.y = hi32(acc[i][0]) + b1;
        o0.z = lo32(acc[i][1]) + b2; o0.w = hi32(acc[i][1]) + b3;
        o1.x = lo32(acc[i][2]) + b4; o1.y = hi32(acc[i][2]) + b5;
        o1.z = lo32(acc[i][3]) + b6; o1.w = hi32(acc[i][3]) + b7;
        *(float4*)crow = o0;
        *(float4*)(crow + 4) = o1;
    }
}

// LSTM gates (i,f,g,o), activation=None: c'=sig(f)*c+sig(i)*g ; h'=sig(o)*c'
__global__ void k_gates(const float* __restrict__ bias, int KS) {
    int idx = blockIdx.x * blockDim.x + threadIdx.x;
    int b = idx >> 10, j = idx & 1023;
    float zi = bias[j], zf = bias[j + 1024], zg = bias[j + 2048], zo = bias[j + 3072];
    for (int s = 0; s < KS; s++) {
        const float* z = g_z + s * NB * G4H + (b << 12);
        zi = __fadd_rn(zi, z[j]);
        zf = __fadd_rn(zf, z[j + 1024]);
        zg = __fadd_rn(zg, z[j + 2048]);
        zo = __fadd_rn(zo, z[j + 3072]);
    }
    float si = 1.f / (1.f + expf(-zi));
    float sf = 1.f / (1.f + expf(-zf));
    float so = 1.f / (1.f + expf(-zo));
    float cn = __fadd_rn(__fmul_rn(sf, g_c[idx]), __fmul_rn(si, zg));
    g_c[idx] = cn;
    g_h[idx] = __fmul_rn(so, cn);
}

__device__ __forceinline__ void softmerge(float& m, float& S, float& T,
                                          float m2, float S2, float T2) {
    if (S2 == 0.f) return;
    if (S == 0.f) { m = m2; S = S2; T = T2; return; }
    if (m2 > m) {
        float t;
        t = m; m = m2; m2 = t;
        t = S; S = S2; S2 = t;
        t = T; T = T2; T2 = t;
    }
    float e = expf(m2 - m);
    S += S2 * e;
    T += (T2 + (m2 - m) * S2) * e;
}

// pass 1: per-(row, V-slice) online (max, sum e^(l-m), sum (l-m)e^(l-m))
__global__ __launch_bounds__(256) void k_red() {
    int slice = blockIdx.x;   // 0..7
    int row   = blockIdx.y;   // 0..63
    int tid   = threadIdx.x;
    const float* lrow = g_logits + row * NV;
    int v0 = slice * 4000, v1 = v0 + 4000;
    float m = negInf(), S = 0.f, T = 0.f;
    for (int v = v0 + tid; v < v1; v += 256) {
        float l = lrow[v];
        if (S == 0.f) { m = l; S = 1.f; T = 0.f; }
        else if (l > m) {
            float e = expf(m - l);
            T = (T + (m - l) * S) * e;
            S = S * e + 1.f;
            m = l;
        } else {
            float d = l - m, e = expf(d);
            S += e; T += d * e;
        }
    }
    for (int o = 16; o; o >>= 1) {
        float m2 = __shfl_down_sync(0xffffffffu, m, o);
        float S2 = __shfl_down_sync(0xffffffffu, S, o);
        float T2 = __shfl_down_sync(0xffffffffu, T, o);
        softmerge(m, S, T, m2, S2, T2);
    }
    __shared__ float sm[8], sS[8], sT[8];
    if ((tid & 31) == 0) { sm[tid >> 5] = m; sS[tid >> 5] = S; sT[tid >> 5] = T; }
    __syncthreads();
    if (tid == 0) {
        float fm = sm[0], fS = sS[0], fT = sT[0];
        for (int w = 1; w < 8; w++) softmerge(fm, fS, fT, sm[w], sS[w], sT[w]);
        g_red[row * 8 + slice] = make_float4(fm, fS, fT, 0.f);
    }
}

// pass 2: merge red partials locally (identical order), entropy from slice 0,
// gumbel argmax of lp+g (partitionable threefry, XOR fold). Winner partials
// stored per-t; final selection deferred to k_fin.
__global__ __launch_bounds__(256) void k_samp(float* __restrict__ out, int t) {
    int slice = blockIdx.x;    // 0..7
    int row   = blockIdx.y;    // 0..63
    int tid   = threadIdx.x;
    uint32_t kk0, kk1;
    tf2x32(0u, 1234u, 0u, (uint32_t)t, kk0, kk1);   // fold_in(key(1234), t)

    float m = negInf(), S = 0.f, T = 0.f;
    for (int s = 0; s < 8; s++) {
        float4 p = g_red[row * 8 + s];
        softmerge(m, S, T, p.x, p.y, p.z);
    }
    float lS = (float)log((double)S);
    if (slice == 0 && tid == 0)
        out[2 * NB * 2 * NT + row * (2 * NT) + t] = lS - T / S;

    const float* lrow = g_logits + row * NV;
    float best = negInf(), blp = 0.f; int bidx = 0x7fffffff;
    int v0 = slice * 4000, v1 = v0 + 4000;
    for (int v = v0 + tid; v < v1; v += 256) {
        uint32_t i = (uint32_t)(row * NV + v);
        uint32_t o0, o1;
        tf2x32(kk0, kk1, 0u, i, o0, o1);
        float u = u01(o0 ^ o1);
        float g = (float)(-log(-log((double)u)));
        float lp = __fadd_rn(__fadd_rn(lrow[v], -m), -lS);
        float s = __fadd_rn(g, lp);
        if (s > best || (s == best && v < bidx)) { best = s; bidx = v; blp = lp; }
    }
    for (int o = 16; o; o >>= 1) {
        float v2 = __shfl_down_sync(0xffffffffu, best, o);
        int   i2 = __shfl_down_sync(0xffffffffu, bidx, o);
        float l2 = __shfl_down_sync(0xffffffffu, blp, o);
        if (v2 > best || (v2 == best && i2 < bidx)) { best = v2; bidx = i2; blp = l2; }
    }
    __shared__ float sv[8]; __shared__ int si[8]; __shared__ float sl[8];
    if ((tid & 31) == 0) { int w = tid >> 5; sv[w] = best; si[w] = bidx; sl[w] = blp; }
    __syncthreads();
    if (tid == 0) {
        float bv = sv[0]; int bi = si[0]; float bl = sl[0];
        for (int w = 1; w < 8; w++)
            if (sv[w] > bv || (sv[w] == bv && si[w] < bi)) {
                bv = sv[w]; bi = si[w]; bl = sl[w];
            }
        int base = (t * NB + row) * 8 + slice;
        g_aval[base] = bv;
        g_aidx[base] = bi;
        g_alp[base]  = bl;
    }
}

// final winner selection for all t at once
__global__ void k_fin(float* __restrict__ out) {
    int t = blockIdx.x;       // 0..NT-1
    int row = threadIdx.x;    // 0..63
    if (row >= NB) return;
    int base = (t * NB + row) * 8;
    float bv = negInf(); int bi = 0x7fffffff; float bl = 0.f;
    for (int s = 0; s < 8; s++) {
        float v = g_aval[base + s];
        int   i = g_aidx[base + s];
        if (v > bv || (v == bv && i < bi)) { bv = v; bi = i; bl = g_alp[base + s]; }
    }
    out[row * (2 * NT) + t] = (float)bi;                    // msg
    out[NB * 2 * NT + row * (2 * NT) + t] = bl;             // log_prob
}

__global__ void k_copyh(float* __restrict__ out) {
    int i = blockIdx.x * blockDim.x + threadIdx.x;
    if (i < NB * NH) out[3 * NB * 2 * NT + i] = g_h[i];
}

extern "C" void kernel_launch(void* const* d_in, const int* in_sizes, int n_in,
                              void* d_out, int out_size) {
    const float *inp = 0, *Wx1 = 0, *Wd = 0, *bd = 0, *b1 = 0, *b2 = 0;
    const float* w4[3] = {0, 0, 0};
    int n4 = 0;
    for (int i = 0; i < n_in; i++) {
        const float* p = (const float*)d_in[i];
        switch (in_sizes[i]) {
            case 32768:    inp = p; break;
            case 2097152:  Wx1 = p; break;
            case 4194304:  if (n4 < 3) w4[n4++] = p; break;
            case 32768000: Wd = p; break;
            case 32000:    bd = p; break;
            case 4096:     if (!b1) b1 = p; else b2 = p; break;
            default: break;
        }
    }
    float* out = (float*)d_out;

    void *pz, *plog, *ph, *pw2;
    cudaGetSymbolAddress(&pz, g_z);
    cudaGetSymbolAddress(&plog, g_logits);
    cudaGetSymbolAddress(&ph, g_h);
    cudaGetSymbolAddress(&pw2, g_W2);
    float* z  = (float*)pz;
    float* lg = (float*)plog;
    float* h  = (float*)ph;
    float* W2 = (float*)pw2;

    k_init<<<256, 256>>>(out);
    k_addw<<<(NH * G4H) / 256, 256>>>(w4[1], w4[2]);

    // encoder: one step, zero state -> z = inp @ Wx1 + b1
    gemm64<<<dim3(64, 2), 256>>>(inp, Wx1, b1, z, 512, G4H);
    k_gates<<<256, 256>>>(b1, 2);

    for (int t = 0; t < NT; t++) {
        gemm64<<<dim3(64, 2), 256>>>(h, W2, b2, z, NH, G4H);
        k_gates<<<256, 256>>>(b2, 2);
        gemmL<<<250, 128>>>(h, Wd, bd, lg);
        k_red<<<dim3(8, 64), 256>>>();
        k_samp<<<dim3(8, 64), 256>>>(out, t);
    }
    k_fin<<<NT, 64>>>(out);
    k_copyh<<<256, 256>>>(out);
}